// round 10
// baseline (speedup 1.0000x reference)
#include <cuda_runtime.h>
#include <cstdint>
#include <math.h>

// ---------------------------------------------------------------------------
// DeformableConv2d: B=8, C=112, H=W=64, O=112, K=3, G=14, stride=1, pad=1
// pg channels: 378 = 252 offsets (interleaved dy/dx per (g,k)) + 126 mask
// ---------------------------------------------------------------------------

#define BB 8
#define CC 112
#define HH 64
#define WW 64
#define OO 112
#define GG 14
#define K2 9
#define PGC 378            // 3*G*K2
#define HW 4096            // 64*64
#define CK 1008            // C*K2

// scratch (allocation-free rule: static __device__ arrays)
__device__ float g_pg[BB * PGC * HW];          // 47.25 MiB
__device__ float g_smp[BB * CC * K2 * HW];     // 126 MiB

// ---------------------------------------------------------------------------
// Kernel 1: pg = conv3x3(x, pg_weight, pad=1) + pg_bias
// Block: 256 threads -> 128 oc x 128 px (2 output rows). c-chunks of 4.
// Thread tile: 8 oc x 8 px; the 8 oc are split {og*4 .. og*4+3} and
// {og*4+64 .. og*4+67} so both weight float4 reads are subphase-conflict-free
// (bytes 0..127 resp. 256..383 of a 512B-aligned ws row).
// x reads: half-warp shares pg -> broadcast LDS.
// ---------------------------------------------------------------------------
__global__ __launch_bounds__(256) void k1_pgconv(const float* __restrict__ x,
                                                 const float* __restrict__ pw,
                                                 const float* __restrict__ pb)
{
    const int ocTile = blockIdx.x;     // 0..2  (3*128 = 384 >= 378)
    const int rp     = blockIdx.y;     // 0..31 row pair
    const int b      = blockIdx.z;     // 0..7
    const int t      = threadIdx.x;
    const int oh0    = rp * 2;

    const int og   = t & 15;           // 16 oc groups
    const int pg   = t >> 4;           // 16 pixel groups
    const int r    = pg >> 3;          // 0/1 : which output row
    const int col0 = (pg & 7) * 8;     // 8 contiguous columns
    const int oca  = og * 4;           // first oc quad (local)
    const int ocb  = og * 4 + 64;      // second oc quad (local)
    const int oc0  = ocTile * 128;

    // xs rows: input rows oh0-1 .. oh0+2 ; 4 channels per chunk
    __shared__ __align__(16) float xs[4][4][68];
    __shared__ __align__(16) float ws[36 * 128];  // [ck][oc] ck = cl*9+tap

    // halo columns (iw=-1 at [0], iw=64 at [65]) always OOB -> zero once
    if (t < 32) {
        int rr = t >> 3, cl = (t >> 1) & 3, side = t & 1;
        xs[rr][cl][side * 65] = 0.f;
    }

    float acc[8][8];
#pragma unroll
    for (int j = 0; j < 8; ++j)
#pragma unroll
        for (int i = 0; i < 8; ++i) acc[j][i] = 0.f;

    for (int c0 = 0; c0 < CC; c0 += 4) {
        __syncthreads();
        // ---- input tile: 4 rows x 4 ch x 64 inner cols (1024 = 4*256)
        {
            int idx = t;
#pragma unroll
            for (int i = 0; i < 4; ++i, idx += 256) {
                int col = idx & 63;
                int cl  = (idx >> 6) & 3;
                int rr  = idx >> 8;
                int ih  = oh0 - 1 + rr;
                float v = 0.f;
                if ((unsigned)ih < 64u)
                    v = x[(((size_t)b * CC + c0 + cl) * HH + ih) * WW + col];
                xs[rr][cl][col + 1] = v;
            }
        }
        // ---- weight tile: 36 ck x 128 oc (4608 = 18*256), [ck][oc]
        {
            int idx = t;
#pragma unroll
            for (int i = 0; i < 18; ++i, idx += 256) {
                int ocl = idx & 127;
                int ck  = idx >> 7;
                int oc  = oc0 + ocl;
                float v = (oc < PGC) ? pw[(size_t)oc * CK + c0 * 9 + ck] : 0.f;
                ws[ck * 128 + ocl] = v;
            }
        }
        __syncthreads();

#pragma unroll
        for (int cl = 0; cl < 4; ++cl) {
#pragma unroll
            for (int ky = 0; ky < 3; ++ky) {
                // 10 consecutive floats; half-warp shares pg -> broadcast
                const float* xrow = &xs[r + ky][cl][col0];
                const float4 xa = *(const float4*)(xrow);
                const float4 xb = *(const float4*)(xrow + 4);
                const float2 xc = *(const float2*)(xrow + 8);
                const float xv[10] = { xa.x, xa.y, xa.z, xa.w,
                                       xb.x, xb.y, xb.z, xb.w,
                                       xc.x, xc.y };
#pragma unroll
                for (int kx = 0; kx < 3; ++kx) {
                    const float* wrow = &ws[(cl * 9 + ky * 3 + kx) * 128];
                    const float4 wv0 = *(const float4*)(wrow + oca);
                    const float4 wv1 = *(const float4*)(wrow + ocb);
#pragma unroll
                    for (int i = 0; i < 8; ++i) {
                        const float xvi = xv[i + kx];
                        acc[0][i] = fmaf(wv0.x, xvi, acc[0][i]);
                        acc[1][i] = fmaf(wv0.y, xvi, acc[1][i]);
                        acc[2][i] = fmaf(wv0.z, xvi, acc[2][i]);
                        acc[3][i] = fmaf(wv0.w, xvi, acc[3][i]);
                        acc[4][i] = fmaf(wv1.x, xvi, acc[4][i]);
                        acc[5][i] = fmaf(wv1.y, xvi, acc[5][i]);
                        acc[6][i] = fmaf(wv1.z, xvi, acc[6][i]);
                        acc[7][i] = fmaf(wv1.w, xvi, acc[7][i]);
                    }
                }
            }
        }
    }

#pragma unroll
    for (int j = 0; j < 8; ++j) {
        int ocl = (j < 4) ? (oca + j) : (ocb + j - 4);
        int oc  = oc0 + ocl;
        if (oc < PGC) {
            float bv = pb[oc];
            float* dst = &g_pg[(((size_t)b * PGC + oc) * HH + oh0 + r) * WW + col0];
            float4 v0 = make_float4(acc[j][0] + bv, acc[j][1] + bv,
                                    acc[j][2] + bv, acc[j][3] + bv);
            float4 v1 = make_float4(acc[j][4] + bv, acc[j][5] + bv,
                                    acc[j][6] + bv, acc[j][7] + bv);
            *(float4*)(dst)     = v0;
            *(float4*)(dst + 4) = v1;
        }
    }
}

// ---------------------------------------------------------------------------
// Kernel 2: bilinear sampling * sigmoid(mask)
// One thread per (b, g, k, pixel). dy = pg[g*18+2k], dx = pg[g*18+2k+1]
// (interleaved!), mask = sigmoid(pg[252 + g*9 + k]).
// Output layout: g_smp[b][c][k][p]
// ---------------------------------------------------------------------------
__global__ __launch_bounds__(256) void k2_sample(const float* __restrict__ x)
{
    int gid = blockIdx.x * 256 + threadIdx.x;
    const int TOT = BB * GG * K2 * HW;   // 4,128,768
    if (gid >= TOT) return;

    int p    = gid & (HW - 1);
    int rest = gid >> 12;
    int gk   = rest % (GG * K2);
    int b    = rest / (GG * K2);
    int g    = gk / 9;
    int k    = gk - g * 9;
    int oh   = p >> 6, ow = p & 63;

    const float* pgb = g_pg + (size_t)b * PGC * HW;
    float dy = pgb[(g * 18 + 2 * k) * HW + p];
    float dx = pgb[(g * 18 + 2 * k + 1) * HW + p];
    float m  = pgb[(252 + gk) * HW + p];
    float mask = 1.f / (1.f + expf(-m));

    float yy = (float)(oh - 1 + k / 3) + dy;
    float xx = (float)(ow - 1 + k % 3) + dx;
    float y0f = floorf(yy), x0f = floorf(xx);
    float wy1 = yy - y0f, wx1 = xx - x0f;
    float wy0 = 1.f - wy1, wx0 = 1.f - wx1;
    int y0 = (int)y0f, x0i = (int)x0f;
    int y1 = y0 + 1, x1 = x0i + 1;
    bool vy0 = (unsigned)y0 < 64u, vy1 = (unsigned)y1 < 64u;
    bool vx0 = (unsigned)x0i < 64u, vx1 = (unsigned)x1 < 64u;

    float w00 = (vy0 && vx0) ? wy0 * wx0 * mask : 0.f;
    float w01 = (vy0 && vx1) ? wy0 * wx1 * mask : 0.f;
    float w10 = (vy1 && vx0) ? wy1 * wx0 * mask : 0.f;
    float w11 = (vy1 && vx1) ? wy1 * wx1 * mask : 0.f;

    int yc0 = min(max(y0, 0), 63), yc1 = min(max(y1, 0), 63);
    int xc0 = min(max(x0i, 0), 63), xc1 = min(max(x1, 0), 63);
    int i00 = yc0 * 64 + xc0, i01 = yc0 * 64 + xc1;
    int i10 = yc1 * 64 + xc0, i11 = yc1 * 64 + xc1;

    const float* xb = x + ((size_t)b * CC + g * 8) * HW;
    float* out = g_smp + ((((size_t)b * CC + g * 8) * K2) + k) * HW + p;
#pragma unroll
    for (int c = 0; c < 8; ++c) {
        const float* xc = xb + (size_t)c * HW;
        float v = w00 * xc[i00] + w01 * xc[i01] + w10 * xc[i10] + w11 * xc[i11];
        out[(size_t)c * K2 * HW] = v;
    }
}

// ---------------------------------------------------------------------------
// Kernel 3: out[b,o,p] = bias[o] + sum_ck smp[b,ck,p] * W[o,ck]
// Block: 256 threads -> 112 O x 128 px. Thread tile: 7 oc x 8 px. K-chunk 16.
// ---------------------------------------------------------------------------
__global__ __launch_bounds__(256) void k3_gemm(const float* __restrict__ w2,
                                               const float* __restrict__ bias,
                                               float* __restrict__ out)
{
    const int pt = blockIdx.x;       // 0..31
    const int b  = blockIdx.y;       // 0..7
    const int t  = threadIdx.x;
    const int pxg = t & 15;          // 16 groups * 8 px
    const int ocg = t >> 4;          // 16 groups * 7 oc
    const int p0  = pt * 128;
    const int px0 = pxg * 8;

    __shared__ __align__(16) float ss[16 * 128];   // [ckl][px]
    __shared__ float ws2[16 * 113];                // [ckl][o] pad

    float acc[7][8];
#pragma unroll
    for (int j = 0; j < 7; ++j)
#pragma unroll
        for (int i = 0; i < 8; ++i) acc[j][i] = 0.f;

    const float* sb = g_smp + (size_t)b * CK * HW + p0;

    for (int ck0 = 0; ck0 < CK; ck0 += 16) {
        __syncthreads();
        {
            int idx = t;
#pragma unroll
            for (int i = 0; i < 8; ++i, idx += 256) {
                int pxl = idx & 127;
                int ckl = idx >> 7;
                ss[ckl * 128 + pxl] = sb[(size_t)(ck0 + ckl) * HW + pxl];
            }
        }
        {
            int idx = t;
#pragma unroll
            for (int i = 0; i < 7; ++i, idx += 256) {
                int ckl = idx & 15;
                int o   = idx >> 4;
                ws2[ckl * 113 + o] = w2[(size_t)o * CK + ck0 + ckl];
            }
        }
        __syncthreads();

#pragma unroll
        for (int ckl = 0; ckl < 16; ++ckl) {
            float4 sa = *(const float4*)(&ss[ckl * 128 + px0]);
            float4 sc = *(const float4*)(&ss[ckl * 128 + px0 + 4]);
            const float* wr = &ws2[ckl * 113 + ocg * 7];
#pragma unroll
            for (int j = 0; j < 7; ++j) {
                float wv = wr[j];
                acc[j][0] = fmaf(wv, sa.x, acc[j][0]);
                acc[j][1] = fmaf(wv, sa.y, acc[j][1]);
                acc[j][2] = fmaf(wv, sa.z, acc[j][2]);
                acc[j][3] = fmaf(wv, sa.w, acc[j][3]);
                acc[j][4] = fmaf(wv, sc.x, acc[j][4]);
                acc[j][5] = fmaf(wv, sc.y, acc[j][5]);
                acc[j][6] = fmaf(wv, sc.z, acc[j][6]);
                acc[j][7] = fmaf(wv, sc.w, acc[j][7]);
            }
        }
    }

#pragma unroll
    for (int j = 0; j < 7; ++j) {
        int o = ocg * 7 + j;
        float bv = bias[o];
        float* dst = &out[(((size_t)b * OO + o) * HW) + p0 + px0];
        float4 v0 = make_float4(acc[j][0] + bv, acc[j][1] + bv,
                                acc[j][2] + bv, acc[j][3] + bv);
        float4 v1 = make_float4(acc[j][4] + bv, acc[j][5] + bv,
                                acc[j][6] + bv, acc[j][7] + bv);
        *(float4*)(dst)     = v0;
        *(float4*)(dst + 4) = v1;
    }
}

// ---------------------------------------------------------------------------
extern "C" void kernel_launch(void* const* d_in, const int* in_sizes, int n_in,
                              void* d_out, int out_size)
{
    const float* x  = (const float*)d_in[0];   // (8,112,64,64)
    const float* pw = (const float*)d_in[1];   // (378,112,3,3)
    const float* pb = (const float*)d_in[2];   // (378,)
    const float* w  = (const float*)d_in[3];   // (112,112,3,3)
    const float* bs = (const float*)d_in[4];   // (112,)
    float* out = (float*)d_out;                // (8,112,64,64)

    dim3 g1(3, 32, 8);
    k1_pgconv<<<g1, 256>>>(x, pw, pb);

    const int tot2 = BB * GG * K2 * HW;
    k2_sample<<<(tot2 + 255) / 256, 256>>>(x);

    dim3 g3(32, 8);
    k3_gemm<<<g3, 256>>>(w, bs, out);
}

// round 13
// speedup vs baseline: 1.2100x; 1.2100x over previous
#include <cuda_runtime.h>
#include <cstdint>
#include <math.h>

// ---------------------------------------------------------------------------
// DeformableConv2d: B=8, C=112, H=W=64, O=112, K=3, G=14, stride=1, pad=1
// pg channels: 378 = 252 offsets (interleaved dy/dx per (g,k)) + 126 mask
// ---------------------------------------------------------------------------

#define BB 8
#define CC 112
#define HH 64
#define WW 64
#define OO 112
#define GG 14
#define K2 9
#define PGC 378            // 3*G*K2
#define HW 4096            // 64*64
#define CK 1008            // C*K2

// scratch (allocation-free rule: static __device__ arrays)
__device__ float g_pg[BB * PGC * HW];          // 47.25 MiB

// ---------------------------------------------------------------------------
// Kernel 1 (R9 winner): pg = conv3x3(x, pg_weight, pad=1) + pg_bias
// Block: 256 threads -> 64 oc x 128 px (2 output rows). c-chunks of 8.
// Thread map: og = t&15, pg = t>>4 (x broadcast, w conflict-free).
// Thread tile: 4 oc x 8 px.
// ---------------------------------------------------------------------------
__global__ __launch_bounds__(256) void k1_pgconv(const float* __restrict__ x,
                                                 const float* __restrict__ pw,
                                                 const float* __restrict__ pb)
{
    const int ocTile = blockIdx.x;     // 0..5  (6*64 = 384 >= 378)
    const int rp     = blockIdx.y;     // 0..31 row pair
    const int b      = blockIdx.z;     // 0..7
    const int t      = threadIdx.x;
    const int oh0    = rp * 2;

    const int og   = t & 15;           // 16 oc groups * 4 oc
    const int pg   = t >> 4;           // 16 pixel groups
    const int r    = pg >> 3;          // 0/1 : which output row
    const int col0 = (pg & 7) * 8;     // 8 contiguous columns
    const int ocl0 = og * 4;
    const int oc0  = ocTile * 64;

    __shared__ __align__(16) float xs[4][8][68];
    __shared__ __align__(16) float ws[72 * 64];   // [ck][oc]

    // halo columns (iw=-1 at [0], iw=64 at [65]) always OOB -> zero once
    if (t < 64) {
        int rr = t >> 4, cl = (t >> 1) & 7, side = t & 1;
        xs[rr][cl][side * 65] = 0.f;
    }

    float acc[4][8];
#pragma unroll
    for (int j = 0; j < 4; ++j)
#pragma unroll
        for (int i = 0; i < 8; ++i) acc[j][i] = 0.f;

    for (int c0 = 0; c0 < CC; c0 += 8) {
        __syncthreads();
        // ---- input tile: 4 rows x 8 ch x 64 inner cols (2048 = 8*256)
        {
            int idx = t;
#pragma unroll
            for (int i = 0; i < 8; ++i, idx += 256) {
                int col = idx & 63;
                int cl  = (idx >> 6) & 7;
                int rr  = idx >> 9;
                int ih  = oh0 - 1 + rr;
                float v = 0.f;
                if ((unsigned)ih < 64u)
                    v = x[(((size_t)b * CC + c0 + cl) * HH + ih) * WW + col];
                xs[rr][cl][col + 1] = v;
            }
        }
        // ---- weight tile: 72 ck x 64 oc (4608 = 18*256), [ck][oc]
        {
            int idx = t;
#pragma unroll
            for (int i = 0; i < 18; ++i, idx += 256) {
                int ocl = idx & 63;
                int ck  = idx >> 6;
                int oc  = oc0 + ocl;
                float v = (oc < PGC) ? pw[(size_t)oc * CK + c0 * 9 + ck] : 0.f;
                ws[ck * 64 + ocl] = v;
            }
        }
        __syncthreads();

#pragma unroll
        for (int cl = 0; cl < 8; ++cl) {
#pragma unroll
            for (int ky = 0; ky < 3; ++ky) {
                const float* xrow = &xs[r + ky][cl][col0];
                const float4 xa = *(const float4*)(xrow);
                const float4 xb = *(const float4*)(xrow + 4);
                const float2 xc = *(const float2*)(xrow + 8);
                const float xv[10] = { xa.x, xa.y, xa.z, xa.w,
                                       xb.x, xb.y, xb.z, xb.w,
                                       xc.x, xc.y };
#pragma unroll
                for (int kx = 0; kx < 3; ++kx) {
                    const float4 wv =
                        *(const float4*)(&ws[(cl * 9 + ky * 3 + kx) * 64 + ocl0]);
#pragma unroll
                    for (int i = 0; i < 8; ++i) {
                        acc[0][i] = fmaf(wv.x, xv[i + kx], acc[0][i]);
                        acc[1][i] = fmaf(wv.y, xv[i + kx], acc[1][i]);
                        acc[2][i] = fmaf(wv.z, xv[i + kx], acc[2][i]);
                        acc[3][i] = fmaf(wv.w, xv[i + kx], acc[3][i]);
                    }
                }
            }
        }
    }

#pragma unroll
    for (int j = 0; j < 4; ++j) {
        int oc = oc0 + ocl0 + j;
        if (oc < PGC) {
            float bv = pb[oc];
            float* dst = &g_pg[(((size_t)b * PGC + oc) * HH + oh0 + r) * WW + col0];
            float4 v0 = make_float4(acc[j][0] + bv, acc[j][1] + bv,
                                    acc[j][2] + bv, acc[j][3] + bv);
            float4 v1 = make_float4(acc[j][4] + bv, acc[j][5] + bv,
                                    acc[j][6] + bv, acc[j][7] + bv);
            *(float4*)(dst)     = v0;
            *(float4*)(dst + 4) = v1;
        }
    }
}

// ---------------------------------------------------------------------------
// Kernel 2+3 FUSED: sample (bilinear * sigmoid-mask) straight into smem, then
// GEMM-consume it. g_smp eliminated.
// Block: 256 threads -> 112 O x 128 px tile. Thread tile 7 oc x 8 px.
// Loop over g=0..13 and channel-half h=0..1: 36 ck per step.
//   sample: 1152 (k,px) tasks/half, 4 channels each -> ss[36][128]
//   gemm:   36 k-steps vs ws2[36][113]
// ---------------------------------------------------------------------------
__global__ __launch_bounds__(256) void k23_fused(const float* __restrict__ x,
                                                 const float* __restrict__ w2,
                                                 const float* __restrict__ bias,
                                                 float* __restrict__ out)
{
    const int pt = blockIdx.x;       // 0..31
    const int b  = blockIdx.y;       // 0..7
    const int t  = threadIdx.x;
    const int pxg = t & 15;          // 16 groups * 8 px
    const int ocg = t >> 4;          // 16 groups * 7 oc
    const int p0  = pt * 128;
    const int px0 = pxg * 8;

    __shared__ __align__(16) float ss[36 * 128];   // [ckl][px]
    __shared__ float ws2[36 * 113];                // [ckl][o] pad

    float acc[7][8];
#pragma unroll
    for (int j = 0; j < 7; ++j)
#pragma unroll
        for (int i = 0; i < 8; ++i) acc[j][i] = 0.f;

    const float* pgb = g_pg + (size_t)b * PGC * HW;
    const float* xb  = x + (size_t)b * CC * HW;

    for (int g = 0; g < GG; ++g) {
        for (int h = 0; h < 2; ++h) {
            __syncthreads();
            // ---- sample fill: tasks (k 0..8, px 0..127); 4 channels per task
            for (int task = t; task < 9 * 128; task += 256) {
                int px = task & 127;
                int k  = task >> 7;
                int p  = p0 + px;
                int oh = p >> 6, ow = p & 63;

                float dy = pgb[(g * 18 + 2 * k) * HW + p];
                float dx = pgb[(g * 18 + 2 * k + 1) * HW + p];
                float m  = pgb[(252 + g * 9 + k) * HW + p];
                float mask = 1.f / (1.f + expf(-m));

                float yy = (float)(oh - 1 + k / 3) + dy;
                float xx = (float)(ow - 1 + k % 3) + dx;
                float y0f = floorf(yy), x0f = floorf(xx);
                float wy1 = yy - y0f, wx1 = xx - x0f;
                float wy0 = 1.f - wy1, wx0 = 1.f - wx1;
                int y0 = (int)y0f, x0i = (int)x0f;
                int y1 = y0 + 1, x1 = x0i + 1;
                bool vy0 = (unsigned)y0 < 64u, vy1 = (unsigned)y1 < 64u;
                bool vx0 = (unsigned)x0i < 64u, vx1 = (unsigned)x1 < 64u;

                float w00 = (vy0 && vx0) ? wy0 * wx0 * mask : 0.f;
                float w01 = (vy0 && vx1) ? wy0 * wx1 * mask : 0.f;
                float w10 = (vy1 && vx0) ? wy1 * wx0 * mask : 0.f;
                float w11 = (vy1 && vx1) ? wy1 * wx1 * mask : 0.f;

                int yc0 = min(max(y0, 0), 63),  yc1 = min(max(y1, 0), 63);
                int xc0 = min(max(x0i, 0), 63), xc1 = min(max(x1, 0), 63);
                int i00 = yc0 * 64 + xc0, i01 = yc0 * 64 + xc1;
                int i10 = yc1 * 64 + xc0, i11 = yc1 * 64 + xc1;

                const float* xg = xb + ((size_t)(g * 8 + h * 4)) * HW;
#pragma unroll
                for (int cl = 0; cl < 4; ++cl) {
                    const float* xc = xg + (size_t)cl * HW;
                    float v = w00 * xc[i00] + w01 * xc[i01]
                            + w10 * xc[i10] + w11 * xc[i11];
                    ss[(cl * 9 + k) * 128 + px] = v;
                }
            }
            // ---- weight fill: 36 ckl x 112 o = 4032
            {
                int ckbase = g * 72 + h * 36;
                for (int idx = t; idx < 36 * 112; idx += 256) {
                    int o   = idx / 36;
                    int ckl = idx - o * 36;
                    ws2[ckl * 113 + o] = w2[(size_t)o * CK + ckbase + ckl];
                }
            }
            __syncthreads();

            // ---- GEMM consume: 36 k-steps
#pragma unroll 4
            for (int ckl = 0; ckl < 36; ++ckl) {
                float4 sa = *(const float4*)(&ss[ckl * 128 + px0]);
                float4 sc = *(const float4*)(&ss[ckl * 128 + px0 + 4]);
                const float* wr = &ws2[ckl * 113 + ocg * 7];
#pragma unroll
                for (int j = 0; j < 7; ++j) {
                    float wv = wr[j];
                    acc[j][0] = fmaf(wv, sa.x, acc[j][0]);
                    acc[j][1] = fmaf(wv, sa.y, acc[j][1]);
                    acc[j][2] = fmaf(wv, sa.z, acc[j][2]);
                    acc[j][3] = fmaf(wv, sa.w, acc[j][3]);
                    acc[j][4] = fmaf(wv, sc.x, acc[j][4]);
                    acc[j][5] = fmaf(wv, sc.y, acc[j][5]);
                    acc[j][6] = fmaf(wv, sc.z, acc[j][6]);
                    acc[j][7] = fmaf(wv, sc.w, acc[j][7]);
                }
            }
        }
    }

#pragma unroll
    for (int j = 0; j < 7; ++j) {
        int o = ocg * 7 + j;
        float bv = bias[o];
        float* dst = &out[(((size_t)b * OO + o) * HW) + p0 + px0];
        float4 v0 = make_float4(acc[j][0] + bv, acc[j][1] + bv,
                                acc[j][2] + bv, acc[j][3] + bv);
        float4 v1 = make_float4(acc[j][4] + bv, acc[j][5] + bv,
                                acc[j][6] + bv, acc[j][7] + bv);
        *(float4*)(dst)     = v0;
        *(float4*)(dst + 4) = v1;
    }
}

// ---------------------------------------------------------------------------
extern "C" void kernel_launch(void* const* d_in, const int* in_sizes, int n_in,
                              void* d_out, int out_size)
{
    const float* x  = (const float*)d_in[0];   // (8,112,64,64)
    const float* pw = (const float*)d_in[1];   // (378,112,3,3)
    const float* pb = (const float*)d_in[2];   // (378,)
    const float* w  = (const float*)d_in[3];   // (112,112,3,3)
    const float* bs = (const float*)d_in[4];   // (112,)
    float* out = (float*)d_out;                // (8,112,64,64)

    dim3 g1(6, 32, 8);
    k1_pgconv<<<g1, 256>>>(x, pw, pb);

    dim3 g23(32, 8);
    k23_fused<<<g23, 256>>>(x, w, bs, out);
}